// round 9
// baseline (speedup 1.0000x reference)
#include <cuda_runtime.h>
#include <cuda_fp16.h>
#include <cstdint>

// ---------------------------------------------------------------------------
// Shapes: x0 (2,256,200,304) x1 (2,256,100,152) x2 (2,256,50,76) x3 (2,256,25,38)
// boxes (2,512,4) -> 1024 rois; out = 4 levels x (1024,256,7,7) f32 concatenated
// ---------------------------------------------------------------------------
#define NLVL 4
#define CCH  256
#define ROUT 7
#define BINS 49
#define RTOT 1024
#define OUT_LVL_STRIDE 12845056   // 1024*256*49
#define ROI_STRIDE     12544      // 256*49
#define SBUF_PITCHW    129        // words per bin row (128 data + 1 pad; 129%32==1)
#define SBUF_BYTES     (BINS * SBUF_PITCHW * 4)   // 25284 B

// fp16 NHWC scratch: 2*256*(60800+15200+3800+950) = 41,344,000 halves (~83 MB)
__device__ __half g_nhwc[41344000];

__constant__ int   c_H[NLVL]     = {200, 100, 50, 25};
__constant__ int   c_W[NLVL]     = {304, 152, 76, 38};
__constant__ float c_S[NLVL]     = {0.25f, 0.125f, 0.0625f, 0.03125f};
__constant__ int   c_OFF[NLVL]   = {0, 31129600, 38912000, 40857600};
__constant__ int   c_NWT[NLVL]   = {10, 5, 3, 2};
__constant__ int   c_START[NLVL] = {0, 16000, 20000, 21200};

// ---------------------------------------------------------------------------
// NCHW(f32) -> NHWC(f16) transpose; bid_base selects the level range so the
// big level-0 sweep can run concurrently with roi work on levels 1-3.
// ---------------------------------------------------------------------------
__global__ __launch_bounds__(256) void transpose_half_kernel(
    const float* __restrict__ x0, const float* __restrict__ x1,
    const float* __restrict__ x2, const float* __restrict__ x3,
    int bid_base)
{
    __shared__ __half2 tile[32][33];     // [c2][w]

    const int bid = blockIdx.x + bid_base;
    int lvl;
    if      (bid >= c_START[3]) lvl = 3;
    else if (bid >= c_START[2]) lvl = 2;
    else if (bid >= c_START[1]) lvl = 1;
    else                        lvl = 0;

    const int H = c_H[lvl], W = c_W[lvl], nwt = c_NWT[lvl];
    const int r   = bid - c_START[lvl];
    const int z   = r / (nwt * H);
    const int rem = r - z * (nwt * H);
    const int h   = rem / nwt;
    const int wt  = (rem - h * nwt) * 32;
    const int b   = z >> 2;
    const int c0  = (z & 3) * 64;

    const float* src = (lvl == 0) ? x0 : (lvl == 1) ? x1 : (lvl == 2) ? x2 : x3;
    const int tx = threadIdx.x, ty = threadIdx.y;

    const int w = wt + tx;
    if (w < W) {
        const float* s = src + ((size_t)(b * CCH + c0) * H + h) * W + w;
        const size_t plane = (size_t)H * W;
#pragma unroll
        for (int j = 0; j < 4; j++) {
            int c2 = ty + j * 8;
            float lo = s[(size_t)(2 * c2) * plane];
            float hi = s[(size_t)(2 * c2 + 1) * plane];
            tile[c2][tx] = __floats2half2_rn(lo, hi);
        }
    }
    __syncthreads();

    __half2* dst = (__half2*)(g_nhwc + c_OFF[lvl]) +
                   ((size_t)(b * H + h) * W) * (CCH / 2) + (c0 >> 1);
#pragma unroll
    for (int jj = 0; jj < 4; jj++) {
        int wl = ty + jj * 8;
        int ww = wt + wl;
        if (ww < W) dst[(size_t)ww * (CCH / 2) + tx] = tile[tx][wl];
    }
}

// ---------------------------------------------------------------------------
// RoI Align main kernel. blk = blk_base + blockIdx.x = lvl*1024 + roi.
// One warp per bin (256 ch: lane -> 8 ch via one LDG.128 per tap).
// Tap tables (packed uint2: offset, weight-bits) merge duplicate pixel
// offsets; zero-weight taps skipped warp-uniformly. x-taps in fp16 (HFMA2),
// y-combine in packed f32x2 (FFMA2). Staged as half2, pitch 129 words/bin,
// flushed fully coalesced in (c,bin) order.
// ---------------------------------------------------------------------------
extern __shared__ unsigned s_bufu[];

typedef unsigned long long u64t;
union F2U { float2 f; u64t u; };

__global__ __launch_bounds__(256, 6) void roi_align_kernel(const float* __restrict__ boxes,
                                                           float* __restrict__ out,
                                                           int blk_base)
{
    __shared__ uint2 s_y[ROUT][4];   // (offset, f32 wy bits);    y==0 => skip row
    __shared__ uint2 s_x[ROUT][4];   // (offset, half2 wx bits);  y==0 => skip tap

    const int blk = blockIdx.x + blk_base;
    const int lvl = blk >> 10;
    const int roi = blk & 1023;
    const int tid = threadIdx.x;

    const int   H = c_H[lvl];
    const int   W = c_W[lvl];
    const float S = c_S[lvl];

    // tap tables: threads 0..6 -> y, 32..38 -> x
    if (tid < ROUT || (tid >= 32 && tid < 32 + ROUT)) {
        const bool isY = (tid < ROUT);
        const int  p   = isY ? tid : (tid - 32);
        const float b1 = boxes[roi * 4 + (isY ? 1 : 0)] * S;
        const float b2 = boxes[roi * 4 + (isY ? 3 : 2)] * S;
        const float len  = fmaxf(b2 - b1, 1.0f);
        const int   D    = isY ? H : W;
        const float Df   = (float)D;
        const float step = len * (1.0f / (float)ROUT);
        const int   estr = isY ? (W * CCH) : CCH;   // strides in halves

        int   off[4];
        float wv[4];
#pragma unroll
        for (int s = 0; s < 2; s++) {
            float g   = ((float)(p * 2 + s) + 0.5f) * 0.5f;
            float pos = b1 + step * g;
            bool  v   = (pos >= -1.0f) && (pos <= Df);
            float pc  = fminf(fmaxf(pos, 0.0f), Df - 1.0f);
            int   i0  = (int)floorf(pc);
            int   i1  = min(i0 + 1, D - 1);
            float l   = pc - (float)i0;
            float hgt = 1.0f - l;
            float vw  = v ? 0.5f : 0.0f;   // 0.5*0.5 realizes the sr^2 mean
            off[2 * s]     = i0 * estr;  wv[2 * s]     = hgt * vw;
            off[2 * s + 1] = i1 * estr;  wv[2 * s + 1] = l * vw;
        }
        // merge duplicate offsets (also covers border-clamped i0==i1)
#pragma unroll
        for (int k = 1; k < 4; k++) {
#pragma unroll
            for (int m = 0; m < k; m++) {
                if (off[k] == off[m] && wv[k] != 0.0f && wv[m] != 0.0f) {
                    wv[m] += wv[k];
                    wv[k] = 0.0f;
                }
            }
        }
        if (isY) {
#pragma unroll
            for (int k = 0; k < 4; k++)
                s_y[p][k] = make_uint2((unsigned)off[k], __float_as_uint(wv[k]));
        } else {
#pragma unroll
            for (int k = 0; k < 4; k++) {
                __half2 h2 = __float2half2_rn(wv[k]);
                s_x[p][k] = make_uint2((unsigned)off[k], *(unsigned*)&h2);
            }
        }
    }
    __syncthreads();

    const int b = roi >> 9;
    const __half* fbase = g_nhwc + c_OFF[lvl] + (size_t)b * H * W * CCH;
    float* outR = out + (size_t)lvl * OUT_LVL_STRIDE + (size_t)roi * ROI_STRIDE;

    const int warp = tid >> 5;
    const int lane = tid & 31;
    const int cbase = lane * 8;     // 8 channels per lane

    for (int bin = warp; bin < BINS; bin += 8) {
        const int ph = bin / 7;
        const int pw = bin - ph * 7;

        u64t acc0 = 0, acc1 = 0, acc2 = 0, acc3 = 0;
#pragma unroll
        for (int i = 0; i < 4; i++) {
            const uint2 yt = s_y[ph][i];
            if (yt.y == 0) continue;                   // warp-uniform: skip 4 LDGs
            const u64t wy2 = ((u64t)yt.y << 32) | yt.y;
            const __half* rp = fbase + yt.x + cbase;
            __half2 r0 = __float2half2_rn(0.f), r1 = r0, r2 = r0, r3 = r0;
#pragma unroll
            for (int j = 0; j < 4; j++) {
                const uint2 xt = s_x[pw][j];
                if (xt.y == 0) continue;               // warp-uniform: skip 1 LDG
                const __half2 w2 = *(const __half2*)&xt.y;
                const uint4 v = *(const uint4*)(rp + xt.x);
                const __half2* hp = (const __half2*)&v;
                r0 = __hfma2(w2, hp[0], r0);
                r1 = __hfma2(w2, hp[1], r1);
                r2 = __hfma2(w2, hp[2], r2);
                r3 = __hfma2(w2, hp[3], r3);
            }
            F2U f0, f1, f2, f3;
            f0.f = __half22float2(r0);
            f1.f = __half22float2(r1);
            f2.f = __half22float2(r2);
            f3.f = __half22float2(r3);
            asm("fma.rn.f32x2 %0, %1, %2, %0;" : "+l"(acc0) : "l"(f0.u), "l"(wy2));
            asm("fma.rn.f32x2 %0, %1, %2, %0;" : "+l"(acc1) : "l"(f1.u), "l"(wy2));
            asm("fma.rn.f32x2 %0, %1, %2, %0;" : "+l"(acc2) : "l"(f2.u), "l"(wy2));
            asm("fma.rn.f32x2 %0, %1, %2, %0;" : "+l"(acc3) : "l"(f3.u), "l"(wy2));
        }

        // stage as half2: word k*32+lane holds channels (cbase+2k, cbase+2k+1)
        F2U o0, o1, o2, o3;
        o0.u = acc0; o1.u = acc1; o2.u = acc2; o3.u = acc3;
        __half2 p0 = __floats2half2_rn(o0.f.x, o0.f.y);
        __half2 p1 = __floats2half2_rn(o1.f.x, o1.f.y);
        __half2 p2 = __floats2half2_rn(o2.f.x, o2.f.y);
        __half2 p3 = __floats2half2_rn(o3.f.x, o3.f.y);
        const int rb = bin * SBUF_PITCHW;
        s_bufu[rb + 0 * 32 + lane] = *(unsigned*)&p0;
        s_bufu[rb + 1 * 32 + lane] = *(unsigned*)&p1;
        s_bufu[rb + 2 * 32 + lane] = *(unsigned*)&p2;
        s_bufu[rb + 3 * 32 + lane] = *(unsigned*)&p3;
    }
    __syncthreads();

    // flush: out element e = c*49 + bin, fully coalesced STG.32.
    int e = tid;
    int c = tid / BINS;
    int bin = tid - c * BINS;
#pragma unroll 7
    for (int it = 0; it < BINS; it++) {
        unsigned wbits = s_bufu[bin * SBUF_PITCHW + (((c & 7) >> 1) << 5) + (c >> 3)];
        __half2 h2 = *(__half2*)&wbits;
        float2 f = __half22float2(h2);
        outR[e] = (c & 1) ? f.y : f.x;
        e += 256;
        bin += 11; c += 5;                 // 256 = 5*49 + 11
        if (bin >= BINS) { bin -= BINS; c += 1; }
    }
}

// ---------------------------------------------------------------------------
// Two-stream graph: transpose(L1-3) -> {roi(L1-3) on side stream || transpose(L0)
// -> roi(L0) on main}; join at end. Streams/events created lazily on the first
// (uncaptured) correctness call; no device memory is allocated.
// ---------------------------------------------------------------------------
static cudaStream_t g_s2 = 0;
static cudaEvent_t  g_evA = 0, g_evB = 0;

extern "C" void kernel_launch(void* const* d_in, const int* in_sizes, int n_in,
                              void* d_out, int out_size)
{
    const float* x0 = (const float*)d_in[0];
    const float* x1 = (const float*)d_in[1];
    const float* x2 = (const float*)d_in[2];
    const float* x3 = (const float*)d_in[3];
    const float* boxes = (const float*)d_in[4];
    float* out = (float*)d_out;

    if (!g_s2) {
        cudaStreamCreateWithFlags(&g_s2, cudaStreamNonBlocking);
        cudaEventCreateWithFlags(&g_evA, cudaEventDisableTiming);
        cudaEventCreateWithFlags(&g_evB, cudaEventDisableTiming);
        cudaFuncSetAttribute(roi_align_kernel,
                             cudaFuncAttributeMaxDynamicSharedMemorySize, SBUF_BYTES);
    }

    // main stream: small-level transpose (bids 16000..21599)
    transpose_half_kernel<<<5600, dim3(32, 8)>>>(x0, x1, x2, x3, 16000);
    cudaEventRecord(g_evA, 0);

    // main stream: level-0 transpose (bids 0..15999), then level-0 roi
    transpose_half_kernel<<<16000, dim3(32, 8)>>>(x0, x1, x2, x3, 0);

    // side stream: roi for levels 1..3, overlapped with level-0 transpose
    cudaStreamWaitEvent(g_s2, g_evA, 0);
    roi_align_kernel<<<3 * RTOT, 256, SBUF_BYTES, g_s2>>>(boxes, out, 1024);
    cudaEventRecord(g_evB, g_s2);

    roi_align_kernel<<<RTOT, 256, SBUF_BYTES>>>(boxes, out, 0);

    // join
    cudaStreamWaitEvent(0, g_evB, 0);
}